// round 16
// baseline (speedup 1.0000x reference)
#include <cuda_runtime.h>
#include <cuda_bf16.h>
#include <cstdint>

#define NUM_USERS 200000
#define NUM_ITEMS 100000
#define NUM_NODES (NUM_USERS + NUM_ITEMS)
#define NUM_EDGES 600000
#define DIM 128
#define BATCH 16384
#define BPB 128
#define S 132   // smem row stride (floats): conflict-free fragment access

// ---------------- scratch (static device globals) ---------------------------
// INVARIANT: g_mask is all-zero at entry to every kernel_launch call.
__device__ __align__(16) float g_agg[(size_t)NUM_NODES * DIM];
__device__ __align__(16) unsigned char g_mask[NUM_NODES];
__device__ __align__(16) float g_M[DIM * DIM];      // W^T W, tf32-rounded (symmetric)
__device__ __align__(16) float g_v[DIM];            // W^T b (fp32)
__device__ float g_c;                               // b.b

__device__ __forceinline__ float tf32r(float x) {
    unsigned u = __float_as_uint(x);
    u = (u + 0x1000u) & 0xFFFFE000u;
    return __uint_as_float(u);
}
__device__ __forceinline__ uint32_t smem_u32(const void* p) {
    uint32_t a;
    asm("{ .reg .u64 t; cvta.to.shared.u64 t, %1; cvt.u32.u64 %0, t; }" : "=r"(a) : "l"(p));
    return a;
}
__device__ __forceinline__ void cp16(uint32_t saddr, const void* gp) {
    size_t ga = __cvta_generic_to_global(gp);
    asm volatile("cp.async.cg.shared.global [%0], [%1], 16;" :: "r"(saddr), "l"(ga) : "memory");
}
#define CP_COMMIT()  asm volatile("cp.async.commit_group;" ::: "memory")
#define CP_WAIT(n)   asm volatile("cp.async.wait_group %0;" :: "n"(n) : "memory")
__device__ __forceinline__ void red4(float* a, float4 v) {
    asm volatile("red.global.add.v4.f32 [%0], {%1, %2, %3, %4};"
                 :: "l"(a), "f"(v.x), "f"(v.y), "f"(v.z), "f"(v.w) : "memory");
}
#define MMA_TF32(acc, a, b) \
    asm volatile( \
        "mma.sync.aligned.m16n8k8.row.col.f32.tf32.tf32.f32 " \
        "{%0,%1,%2,%3}, {%4,%5,%6,%7}, {%8,%9}, {%0,%1,%2,%3};" \
        : "+f"((acc)[0]), "+f"((acc)[1]), "+f"((acc)[2]), "+f"((acc)[3]) \
        : "r"((a)[0]), "r"((a)[1]), "r"((a)[2]), "r"((a)[3]), \
          "r"((b)[0]), "r"((b)[1]))

// ---------------- K_m (side stream, ONE block): tensor-core W^T W ------------
// Stage W (64KB) via cp.async, v = W^T b from unrounded Ws, round Ws to tf32,
// then 16 warps compute C = W^T W with m16n8k8 (transposed smem indexing).
#define SMEM_KM (DIM * S * 4 + 512)
__global__ void __launch_bounds__(512) k_m(const float* __restrict__ W,
                                           const float* __restrict__ b) {
    extern __shared__ char smw[];
    float* Ws = (float*)smw;                    // [j][c] stride S
    float* bs = (float*)(smw + DIM * S * 4);    // 128 floats
    uint32_t sb = smem_u32(smw);
    int tid = threadIdx.x, warp = tid >> 5, lane = tid & 31;
    int g = lane >> 2, t = lane & 3;

    // stage W + b
#pragma unroll
    for (int i = tid; i < DIM * DIM / 4; i += 512) {
        int r = i >> 5, c4 = i & 31;
        cp16(sb + (r * S + 4 * c4) * 4, (const char*)W + (r * DIM + 4 * c4) * 4);
    }
    if (tid < 32) cp16(sb + DIM * S * 4 + tid * 16, (const char*)b + tid * 16);
    CP_COMMIT(); CP_WAIT(0);
    __syncthreads();

    // v = W^T b (unrounded), c = b.b
    if (tid < DIM) {
        float vv = 0.f;
#pragma unroll 8
        for (int j = 0; j < DIM; j++) vv += bs[j] * Ws[j * S + tid];
        g_v[tid] = vv;
        if (tid == 0) {
            float s = 0.f;
#pragma unroll 8
            for (int j = 0; j < DIM; j++) s += bs[j] * bs[j];
            g_c = s;
        }
    }
    __syncthreads();

    // round Ws to tf32 (RN) in place
#pragma unroll
    for (int i = tid; i < DIM * DIM / 4; i += 512) {
        int r = i >> 5, c4 = i & 31;
        float4* p = (float4*)&Ws[r * S + 4 * c4];
        float4 v = *p;
        v.x = tf32r(v.x); v.y = tf32r(v.y); v.z = tf32r(v.z); v.w = tf32r(v.w);
        *p = v;
    }
    __syncthreads();

    // C[m][n] = sum_k Ws[k][m]*Ws[k][n]; warp tile 32x32
    int m0 = (warp & 3) * 32, n0 = (warp >> 2) * 32;
    float acc[2][4][4];
#pragma unroll
    for (int mi = 0; mi < 2; mi++)
#pragma unroll
        for (int ni = 0; ni < 4; ni++)
#pragma unroll
            for (int q = 0; q < 4; q++) acc[mi][ni][q] = 0.f;

#pragma unroll
    for (int k0 = 0; k0 < DIM; k0 += 8) {
        uint32_t a[2][4], bb[4][2];
        const float* w0 = Ws + (k0 + t) * S;
        const float* w4 = Ws + (k0 + t + 4) * S;
#pragma unroll
        for (int mi = 0; mi < 2; mi++) {
            int m = m0 + 16 * mi + g;
            a[mi][0] = __float_as_uint(w0[m]);
            a[mi][1] = __float_as_uint(w0[m + 8]);
            a[mi][2] = __float_as_uint(w4[m]);
            a[mi][3] = __float_as_uint(w4[m + 8]);
        }
#pragma unroll
        for (int ni = 0; ni < 4; ni++) {
            int n = n0 + 8 * ni + g;
            bb[ni][0] = __float_as_uint(w0[n]);
            bb[ni][1] = __float_as_uint(w4[n]);
        }
#pragma unroll
        for (int mi = 0; mi < 2; mi++)
#pragma unroll
            for (int ni = 0; ni < 4; ni++)
                MMA_TF32(acc[mi][ni], a[mi], bb[ni]);
    }

    // store tf32-rounded M
#pragma unroll
    for (int mi = 0; mi < 2; mi++)
#pragma unroll
        for (int ni = 0; ni < 4; ni++) {
            int r0 = m0 + 16 * mi + g, c0 = n0 + 8 * ni + 2 * t;
            g_M[r0 * DIM + c0]           = tf32r(acc[mi][ni][0]);
            g_M[r0 * DIM + c0 + 1]       = tf32r(acc[mi][ni][1]);
            g_M[(r0 + 8) * DIM + c0]     = tf32r(acc[mi][ni][2]);
            g_M[(r0 + 8) * DIM + c0 + 1] = tf32r(acc[mi][ni][3]);
        }
}

// ---------------- K_mark (main stream): mark needed nodes + zero agg rows ----
#define MARKBLOCKS (2 * BATCH / 32)
__global__ void k_mark(const int* __restrict__ ui, const int* __restrict__ ii) {
    int warp = threadIdx.x >> 5, lane = threadIdx.x & 31;
    int rowbase = blockIdx.x * 32 + warp * 4;
    int nodes[4];
#pragma unroll
    for (int q = 0; q < 4; q++) {
        int ref = rowbase + q;
        nodes[q] = (ref < BATCH) ? __ldg(&ui[ref])
                                 : (NUM_USERS + __ldg(&ii[ref - BATCH]));
    }
    const float4 z = make_float4(0.f, 0.f, 0.f, 0.f);
#pragma unroll
    for (int q = 0; q < 4; q++)
        ((float4*)(g_agg + (size_t)nodes[q] * DIM))[lane] = z;
    if (lane == 0) {
#pragma unroll
        for (int q = 0; q < 4; q++) g_mask[nodes[q]] = 1;
    }
}

// ---------------- K1: scan edges; 4 passing edges processed in parallel ------
__global__ void k_edge(const int* __restrict__ src, const int* __restrict__ dst,
                       const float* __restrict__ uemb, const float* __restrict__ iemb) {
    int e = blockIdx.x * blockDim.x + threadIdx.x;
    int lane = threadIdx.x & 31;
    int grp = lane >> 3, sub = lane & 7;
    bool pass = false;
    int d = 0, s = 0;
    if (e < NUM_EDGES) {
        d = dst[e];
        pass = (g_mask[d] != 0);
        if (pass) s = src[e];
    }
    unsigned m = __ballot_sync(0xffffffffu, pass);
    while (m) {
        int cnt = __popc(m);
        int take = cnt < 4 ? cnt : 4;
        bool act = grp < take;
        int bit = act ? __fns(m, 0, grp + 1) : 0;
        int ds = __shfl_sync(0xffffffffu, d, bit);
        int ss = __shfl_sync(0xffffffffu, s, bit);
        if (act) {
            const float* sp = (ss < NUM_USERS)
                                ? (uemb + (size_t)ss * DIM)
                                : (iemb + (size_t)(ss - NUM_USERS) * DIM);
            const float4* sp4 = (const float4*)sp;
            float4 v0 = sp4[sub], v1 = sp4[sub + 8], v2 = sp4[sub + 16], v3 = sp4[sub + 24];
            float* a = g_agg + (size_t)ds * DIM;
            red4(a + sub * 4,        v0);
            red4(a + (sub + 8) * 4,  v1);
            red4(a + (sub + 16) * 4, v2);
            red4(a + (sub + 24) * 4, v3);
        }
#pragma unroll
        for (int q = 0; q < 4; q++)
            if (q < take) m &= m - 1;
    }
}

// ---------------- K2: mma.sync tf32 GEMM + fused bilinear epilogue -----------
#define MS_OFF   0
#define XI_OFF   (DIM * S * 4)
#define XU_OFF   (2 * DIM * S * 4)
#define VV_OFF   (3 * DIM * S * 4)
#define NDI_OFF  (VV_OFF + 512)
#define NDU_OFF  (NDI_OFF + 512)
#define PART_OFF (NDU_OFF + 512)
#define SMEM_K3  (PART_OFF + 2048)

__global__ void __launch_bounds__(512) k_pairs(
    const int* __restrict__ ui, const int* __restrict__ ii,
    float* __restrict__ out)
{
    extern __shared__ char sm[];
    uint32_t sbase = smem_u32(sm);
    float* Msm  = (float*)(sm + MS_OFF);
    float* XIs  = (float*)(sm + XI_OFF);
    float* XUs  = (float*)(sm + XU_OFF);
    float* Vv   = (float*)(sm + VV_OFF);
    int*   Ndi  = (int*)(sm + NDI_OFF);
    int*   Ndu  = (int*)(sm + NDU_OFF);
    float* Part = (float*)(sm + PART_OFF);

    int tid = threadIdx.x, warp = tid >> 5, lane = tid & 31;
    int base = blockIdx.x * BPB;
    int g = lane >> 2, t = lane & 3;

    if (tid < 128) {
        Ndi[tid] = NUM_USERS + __ldg(&ii[base + tid]);
        Ndu[tid] = __ldg(&ui[base + tid]);
        Vv[tid]  = g_v[tid];
    }
    __syncthreads();

    // group 1: XI gather
#pragma unroll
    for (int it = 0; it < 8; it++) {
        int idx = it * 512 + tid;
        int row = idx >> 5, f4 = idx & 31;
        cp16(sbase + XI_OFF + (row * S + 4 * f4) * 4,
             g_agg + (size_t)Ndi[row] * DIM + 4 * f4);
    }
    CP_COMMIT();
    // group 2: M restride
#pragma unroll
    for (int i = tid; i < DIM * DIM / 4; i += 512) {
        int r = i >> 5, c4 = i & 31;
        cp16(sbase + MS_OFF + (r * S + 4 * c4) * 4,
             (const char*)g_M + (r * DIM + 4 * c4) * 4);
    }
    CP_COMMIT();
    // group 3: XU gather
#pragma unroll
    for (int it = 0; it < 8; it++) {
        int idx = it * 512 + tid;
        int row = idx >> 5, f4 = idx & 31;
        cp16(sbase + XU_OFF + (row * S + 4 * f4) * 4,
             g_agg + (size_t)Ndu[row] * DIM + 4 * f4);
    }
    CP_COMMIT();

    CP_WAIT(2);
    __syncthreads();
#pragma unroll
    for (int i = tid; i < DIM * DIM / 4; i += 512) {
        int row = i >> 5, f4 = i & 31;
        float4* p = (float4*)&XIs[row * S + 4 * f4];
        float4 v = *p;
        v.x = tf32r(v.x); v.y = tf32r(v.y); v.z = tf32r(v.z); v.w = tf32r(v.w);
        *p = v;
    }
    if (tid < 128) {
        g_mask[Ndi[tid]] = 0;
        g_mask[Ndu[tid]] = 0;
    }
    CP_WAIT(1);
    __syncthreads();

    int m0 = (warp & 3) * 32, j0 = (warp >> 2) * 32;
    float acc[2][4][4];
#pragma unroll
    for (int mi = 0; mi < 2; mi++)
#pragma unroll
        for (int ni = 0; ni < 4; ni++)
#pragma unroll
            for (int q = 0; q < 4; q++) acc[mi][ni][q] = 0.f;

#pragma unroll
    for (int k0 = 0; k0 < DIM; k0 += 8) {
        uint32_t a[2][4], b[4][2];
#pragma unroll
        for (int mi = 0; mi < 2; mi++) {
            const float* ap = XIs + (m0 + 16 * mi + g) * S + k0 + t;
            a[mi][0] = __float_as_uint(ap[0]);
            a[mi][1] = __float_as_uint(ap[8 * S]);
            a[mi][2] = __float_as_uint(ap[4]);
            a[mi][3] = __float_as_uint(ap[8 * S + 4]);
        }
#pragma unroll
        for (int ni = 0; ni < 4; ni++) {
            const float* bp = Msm + (j0 + 8 * ni + g) * S + k0 + t;
            b[ni][0] = __float_as_uint(bp[0]);
            b[ni][1] = __float_as_uint(bp[4]);
        }
#pragma unroll
        for (int mi = 0; mi < 2; mi++)
#pragma unroll
            for (int ni = 0; ni < 4; ni++)
                MMA_TF32(acc[mi][ni], a[mi], b[ni]);
    }

    CP_WAIT(0);
    __syncthreads();

    int nw = warp >> 2;
#pragma unroll
    for (int mi = 0; mi < 2; mi++) {
        int r_lo = m0 + 16 * mi + g;
        int r_hi = r_lo + 8;
        float plo = 0.f, phi = 0.f;
#pragma unroll
        for (int ni = 0; ni < 4; ni++) {
            int j = j0 + 8 * ni + 2 * t;
            float2 vl  = *(const float2*)&Vv[j];
            float2 xul = *(const float2*)&XUs[r_lo * S + j];
            float2 xuh = *(const float2*)&XUs[r_hi * S + j];
            float2 xil = *(const float2*)&XIs[r_lo * S + j];
            float2 xih = *(const float2*)&XIs[r_hi * S + j];
            plo += xul.x * (acc[mi][ni][0] + vl.x) + xul.y * (acc[mi][ni][1] + vl.y)
                 + vl.x * xil.x + vl.y * xil.y;
            phi += xuh.x * (acc[mi][ni][2] + vl.x) + xuh.y * (acc[mi][ni][3] + vl.y)
                 + vl.x * xih.x + vl.y * xih.y;
        }
        plo += __shfl_xor_sync(0xffffffffu, plo, 1);
        plo += __shfl_xor_sync(0xffffffffu, plo, 2);
        phi += __shfl_xor_sync(0xffffffffu, phi, 1);
        phi += __shfl_xor_sync(0xffffffffu, phi, 2);
        if (t == 0) {
            Part[r_lo * 4 + nw] = plo;
            Part[r_hi * 4 + nw] = phi;
        }
    }
    __syncthreads();

    if (tid < BPB) {
        float r = Part[tid * 4 + 0] + Part[tid * 4 + 1]
                + Part[tid * 4 + 2] + Part[tid * 4 + 3];
        out[base + tid] = r + g_c;
    }
}

// ---------------- launch (fork/join: k_m overlaps mark+edge) -----------------
extern "C" void kernel_launch(void* const* d_in, const int* in_sizes, int n_in,
                              void* d_out, int out_size) {
    const int*   ui   = (const int*)d_in[0];
    const int*   ii   = (const int*)d_in[1];
    const float* uemb = (const float*)d_in[2];
    const float* iemb = (const float*)d_in[3];
    const float* W    = (const float*)d_in[4];
    const float* b    = (const float*)d_in[5];
    const int*   ei   = (const int*)d_in[6];
    const int*   src  = ei;
    const int*   dst  = ei + NUM_EDGES;
    float*       out  = (float*)d_out;

    static cudaStream_t side = nullptr;
    static cudaEvent_t evFork = nullptr, evJoin = nullptr;
    if (!side) {
        cudaStreamCreateWithFlags(&side, cudaStreamNonBlocking);
        cudaEventCreateWithFlags(&evFork, cudaEventDisableTiming);
        cudaEventCreateWithFlags(&evJoin, cudaEventDisableTiming);
        cudaFuncSetAttribute(k_pairs, cudaFuncAttributeMaxDynamicSharedMemorySize, SMEM_K3);
        cudaFuncSetAttribute(k_m,     cudaFuncAttributeMaxDynamicSharedMemorySize, SMEM_KM);
    }

    // fork: side stream computes M/v/c while main stream does mark+edges
    cudaEventRecord(evFork, 0);
    cudaStreamWaitEvent(side, evFork, 0);
    k_m<<<1, 512, SMEM_KM, side>>>(W, b);
    cudaEventRecord(evJoin, side);

    k_mark<<<MARKBLOCKS, 256>>>(ui, ii);
    k_edge<<<(NUM_EDGES + 255) / 256, 256>>>(src, dst, uemb, iemb);

    cudaStreamWaitEvent(0, evJoin, 0);   // join before k_pairs (needs g_M/g_v/g_c)
    k_pairs<<<BATCH / BPB, 512, SMEM_K3>>>(ui, ii, out);
}

// round 17
// speedup vs baseline: 1.1627x; 1.1627x over previous
#include <cuda_runtime.h>
#include <cuda_bf16.h>
#include <cstdint>

#define NUM_USERS 200000
#define NUM_ITEMS 100000
#define NUM_NODES (NUM_USERS + NUM_ITEMS)
#define NUM_EDGES 600000
#define DIM 128
#define BATCH 16384
#define BPB 128
#define S 132   // smem row stride (floats): conflict-free fragment access
#define MASKW ((NUM_NODES + 31) / 32)

// ---------------- scratch (static device globals) ---------------------------
// INVARIANT: g_maskw is all-zero at entry to every kernel_launch call.
__device__ __align__(16) float g_agg[(size_t)NUM_NODES * DIM];
__device__ __align__(16) unsigned int g_maskw[MASKW];   // bitmask (37.5KB, L1-resident)
__device__ __align__(16) float g_M[DIM * DIM];      // W^T W, tf32-rounded (symmetric)
__device__ __align__(16) float g_v[DIM];            // W^T b (fp32)
__device__ float g_c;                               // b.b

__device__ __forceinline__ float tf32r(float x) {
    unsigned u = __float_as_uint(x);
    u = (u + 0x1000u) & 0xFFFFE000u;
    return __uint_as_float(u);
}
__device__ __forceinline__ uint32_t smem_u32(const void* p) {
    uint32_t a;
    asm("{ .reg .u64 t; cvta.to.shared.u64 t, %1; cvt.u32.u64 %0, t; }" : "=r"(a) : "l"(p));
    return a;
}
__device__ __forceinline__ void cp16(uint32_t saddr, const void* gp) {
    size_t ga = __cvta_generic_to_global(gp);
    asm volatile("cp.async.cg.shared.global [%0], [%1], 16;" :: "r"(saddr), "l"(ga) : "memory");
}
#define CP_COMMIT()  asm volatile("cp.async.commit_group;" ::: "memory")
#define CP_WAIT(n)   asm volatile("cp.async.wait_group %0;" :: "n"(n) : "memory")
__device__ __forceinline__ void red4(float* a, float4 v) {
    asm volatile("red.global.add.v4.f32 [%0], {%1, %2, %3, %4};"
                 :: "l"(a), "f"(v.x), "f"(v.y), "f"(v.z), "f"(v.w) : "memory");
}
__device__ __forceinline__ void red_or(unsigned int* a, unsigned int v) {
    asm volatile("red.global.or.b32 [%0], %1;" :: "l"(a), "r"(v) : "memory");
}
__device__ __forceinline__ void red_and(unsigned int* a, unsigned int v) {
    asm volatile("red.global.and.b32 [%0], %1;" :: "l"(a), "r"(v) : "memory");
}
#define MMA_TF32(acc, a, b) \
    asm volatile( \
        "mma.sync.aligned.m16n8k8.row.col.f32.tf32.tf32.f32 " \
        "{%0,%1,%2,%3}, {%4,%5,%6,%7}, {%8,%9}, {%0,%1,%2,%3};" \
        : "+f"((acc)[0]), "+f"((acc)[1]), "+f"((acc)[2]), "+f"((acc)[3]) \
        : "r"((a)[0]), "r"((a)[1]), "r"((a)[2]), "r"((a)[3]), \
          "r"((b)[0]), "r"((b)[1]))

// ---------------- K_m (side stream): M = W^T W (tf32), v = W^T b, c = b.b ----
// (R15 version — 128 blocks, ~2µs, hidden under mark+edge)
__global__ void k_m(const float* __restrict__ W, const float* __restrict__ b) {
    int r = blockIdx.x;      // 0..127
    int c = threadIdx.x;     // 0..127
    float a0 = 0.f, a1 = 0.f, a2 = 0.f, a3 = 0.f;
#pragma unroll
    for (int j = 0; j < DIM; j += 4) {
        a0 += __ldg(&W[(j + 0) * DIM + r]) * __ldg(&W[(j + 0) * DIM + c]);
        a1 += __ldg(&W[(j + 1) * DIM + r]) * __ldg(&W[(j + 1) * DIM + c]);
        a2 += __ldg(&W[(j + 2) * DIM + r]) * __ldg(&W[(j + 2) * DIM + c]);
        a3 += __ldg(&W[(j + 3) * DIM + r]) * __ldg(&W[(j + 3) * DIM + c]);
    }
    g_M[r * DIM + c] = tf32r((a0 + a1) + (a2 + a3));
    if (r == 0) {
        float vv = 0.f;
#pragma unroll 8
        for (int j = 0; j < DIM; j++) vv += __ldg(&b[j]) * __ldg(&W[j * DIM + c]);
        g_v[c] = vv;
        if (c == 0) {
            float s = 0.f;
#pragma unroll 8
            for (int j = 0; j < DIM; j++) s += b[j] * b[j];
            g_c = s;
        }
    }
}

// ---------------- K_mark (main stream): set mask bits + zero agg rows --------
#define MARKBLOCKS (2 * BATCH / 32)
__global__ void k_mark(const int* __restrict__ ui, const int* __restrict__ ii) {
    int warp = threadIdx.x >> 5, lane = threadIdx.x & 31;
    int rowbase = blockIdx.x * 32 + warp * 4;
    int nodes[4];
#pragma unroll
    for (int q = 0; q < 4; q++) {
        int ref = rowbase + q;
        nodes[q] = (ref < BATCH) ? __ldg(&ui[ref])
                                 : (NUM_USERS + __ldg(&ii[ref - BATCH]));
    }
    const float4 z = make_float4(0.f, 0.f, 0.f, 0.f);
#pragma unroll
    for (int q = 0; q < 4; q++)
        ((float4*)(g_agg + (size_t)nodes[q] * DIM))[lane] = z;
    if (lane == 0) {
#pragma unroll
        for (int q = 0; q < 4; q++)
            red_or(&g_maskw[nodes[q] >> 5], 1u << (nodes[q] & 31));
    }
}

// ---------------- K1: scan edges; 4 passing edges processed in parallel ------
__global__ void k_edge(const int* __restrict__ src, const int* __restrict__ dst,
                       const float* __restrict__ uemb, const float* __restrict__ iemb) {
    int e = blockIdx.x * blockDim.x + threadIdx.x;
    int lane = threadIdx.x & 31;
    int grp = lane >> 3, sub = lane & 7;
    bool pass = false;
    int d = 0, s = 0;
    if (e < NUM_EDGES) {
        d = dst[e];
        pass = ((__ldg(&g_maskw[d >> 5]) >> (d & 31)) & 1u) != 0;
        if (pass) s = src[e];
    }
    unsigned m = __ballot_sync(0xffffffffu, pass);
    while (m) {
        int cnt = __popc(m);
        int take = cnt < 4 ? cnt : 4;
        bool act = grp < take;
        int bit = act ? __fns(m, 0, grp + 1) : 0;
        int ds = __shfl_sync(0xffffffffu, d, bit);
        int ss = __shfl_sync(0xffffffffu, s, bit);
        if (act) {
            const float* sp = (ss < NUM_USERS)
                                ? (uemb + (size_t)ss * DIM)
                                : (iemb + (size_t)(ss - NUM_USERS) * DIM);
            const float4* sp4 = (const float4*)sp;
            float4 v0 = sp4[sub], v1 = sp4[sub + 8], v2 = sp4[sub + 16], v3 = sp4[sub + 24];
            float* a = g_agg + (size_t)ds * DIM;
            red4(a + sub * 4,        v0);
            red4(a + (sub + 8) * 4,  v1);
            red4(a + (sub + 16) * 4, v2);
            red4(a + (sub + 24) * 4, v3);
        }
#pragma unroll
        for (int q = 0; q < 4; q++)
            if (q < take) m &= m - 1;
    }
}

// ---------------- K2: mma.sync tf32 GEMM + fused bilinear epilogue -----------
// Pipeline: group1 XI, group2 M, group3 XU -> wait(1) -> MMA -> wait(0) -> epi.
// XI fed to HMMA unrounded: tf32 HMMA truncates low mantissa bits in HW.
#define MS_OFF   0
#define XI_OFF   (DIM * S * 4)
#define XU_OFF   (2 * DIM * S * 4)
#define VV_OFF   (3 * DIM * S * 4)
#define NDI_OFF  (VV_OFF + 512)
#define NDU_OFF  (NDI_OFF + 512)
#define PART_OFF (NDU_OFF + 512)
#define SMEM_K3  (PART_OFF + 2048)

__global__ void __launch_bounds__(512) k_pairs(
    const int* __restrict__ ui, const int* __restrict__ ii,
    float* __restrict__ out)
{
    extern __shared__ char sm[];
    uint32_t sbase = smem_u32(sm);
    float* Msm  = (float*)(sm + MS_OFF);
    float* XIs  = (float*)(sm + XI_OFF);
    float* XUs  = (float*)(sm + XU_OFF);
    float* Vv   = (float*)(sm + VV_OFF);
    int*   Ndi  = (int*)(sm + NDI_OFF);
    int*   Ndu  = (int*)(sm + NDU_OFF);
    float* Part = (float*)(sm + PART_OFF);

    int tid = threadIdx.x, warp = tid >> 5, lane = tid & 31;
    int base = blockIdx.x * BPB;
    int g = lane >> 2, t = lane & 3;

    if (tid < 128) {
        Ndi[tid] = NUM_USERS + __ldg(&ii[base + tid]);
        Ndu[tid] = __ldg(&ui[base + tid]);
        Vv[tid]  = g_v[tid];
    }
    __syncthreads();

    // group 1: XI gather
#pragma unroll
    for (int it = 0; it < 8; it++) {
        int idx = it * 512 + tid;
        int row = idx >> 5, f4 = idx & 31;
        cp16(sbase + XI_OFF + (row * S + 4 * f4) * 4,
             g_agg + (size_t)Ndi[row] * DIM + 4 * f4);
    }
    CP_COMMIT();
    // group 2: M restride
#pragma unroll
    for (int i = tid; i < DIM * DIM / 4; i += 512) {
        int r = i >> 5, c4 = i & 31;
        cp16(sbase + MS_OFF + (r * S + 4 * c4) * 4,
             (const char*)g_M + (r * DIM + 4 * c4) * 4);
    }
    CP_COMMIT();
    // group 3: XU gather
#pragma unroll
    for (int it = 0; it < 8; it++) {
        int idx = it * 512 + tid;
        int row = idx >> 5, f4 = idx & 31;
        cp16(sbase + XU_OFF + (row * S + 4 * f4) * 4,
             g_agg + (size_t)Ndu[row] * DIM + 4 * f4);
    }
    CP_COMMIT();

    // clear this block's mask bits while copies are in flight
    if (tid < 128) {
        red_and(&g_maskw[Ndi[tid] >> 5], ~(1u << (Ndi[tid] & 31)));
        red_and(&g_maskw[Ndu[tid] >> 5], ~(1u << (Ndu[tid] & 31)));
    }

    // wait XI + M; MMA starts (XU still in flight)
    CP_WAIT(1);
    __syncthreads();

    int m0 = (warp & 3) * 32, j0 = (warp >> 2) * 32;
    float acc[2][4][4];
#pragma unroll
    for (int mi = 0; mi < 2; mi++)
#pragma unroll
        for (int ni = 0; ni < 4; ni++)
#pragma unroll
            for (int q = 0; q < 4; q++) acc[mi][ni][q] = 0.f;

#pragma unroll
    for (int k0 = 0; k0 < DIM; k0 += 8) {
        uint32_t a[2][4], b[4][2];
#pragma unroll
        for (int mi = 0; mi < 2; mi++) {
            const float* ap = XIs + (m0 + 16 * mi + g) * S + k0 + t;
            a[mi][0] = __float_as_uint(ap[0]);
            a[mi][1] = __float_as_uint(ap[8 * S]);
            a[mi][2] = __float_as_uint(ap[4]);
            a[mi][3] = __float_as_uint(ap[8 * S + 4]);
        }
#pragma unroll
        for (int ni = 0; ni < 4; ni++) {
            const float* bp = Msm + (j0 + 8 * ni + g) * S + k0 + t;
            b[ni][0] = __float_as_uint(bp[0]);
            b[ni][1] = __float_as_uint(bp[4]);
        }
#pragma unroll
        for (int mi = 0; mi < 2; mi++)
#pragma unroll
            for (int ni = 0; ni < 4; ni++)
                MMA_TF32(acc[mi][ni], a[mi], b[ni]);
    }

    CP_WAIT(0);
    __syncthreads();

    int nw = warp >> 2;
#pragma unroll
    for (int mi = 0; mi < 2; mi++) {
        int r_lo = m0 + 16 * mi + g;
        int r_hi = r_lo + 8;
        float plo = 0.f, phi = 0.f;
#pragma unroll
        for (int ni = 0; ni < 4; ni++) {
            int j = j0 + 8 * ni + 2 * t;
            float2 vl  = *(const float2*)&Vv[j];
            float2 xul = *(const float2*)&XUs[r_lo * S + j];
            float2 xuh = *(const float2*)&XUs[r_hi * S + j];
            float2 xil = *(const float2*)&XIs[r_lo * S + j];
            float2 xih = *(const float2*)&XIs[r_hi * S + j];
            plo += xul.x * (acc[mi][ni][0] + vl.x) + xul.y * (acc[mi][ni][1] + vl.y)
                 + vl.x * xil.x + vl.y * xil.y;
            phi += xuh.x * (acc[mi][ni][2] + vl.x) + xuh.y * (acc[mi][ni][3] + vl.y)
                 + vl.x * xih.x + vl.y * xih.y;
        }
        plo += __shfl_xor_sync(0xffffffffu, plo, 1);
        plo += __shfl_xor_sync(0xffffffffu, plo, 2);
        phi += __shfl_xor_sync(0xffffffffu, phi, 1);
        phi += __shfl_xor_sync(0xffffffffu, phi, 2);
        if (t == 0) {
            Part[r_lo * 4 + nw] = plo;
            Part[r_hi * 4 + nw] = phi;
        }
    }
    __syncthreads();

    if (tid < BPB) {
        float r = Part[tid * 4 + 0] + Part[tid * 4 + 1]
                + Part[tid * 4 + 2] + Part[tid * 4 + 3];
        out[base + tid] = r + g_c;
    }
}

// ---------------- launch (fork/join: k_m overlaps mark+edge) -----------------
extern "C" void kernel_launch(void* const* d_in, const int* in_sizes, int n_in,
                              void* d_out, int out_size) {
    const int*   ui   = (const int*)d_in[0];
    const int*   ii   = (const int*)d_in[1];
    const float* uemb = (const float*)d_in[2];
    const float* iemb = (const float*)d_in[3];
    const float* W    = (const float*)d_in[4];
    const float* b    = (const float*)d_in[5];
    const int*   ei   = (const int*)d_in[6];
    const int*   src  = ei;
    const int*   dst  = ei + NUM_EDGES;
    float*       out  = (float*)d_out;

    static cudaStream_t side = nullptr;
    static cudaEvent_t evFork = nullptr, evJoin = nullptr;
    if (!side) {
        cudaStreamCreateWithFlags(&side, cudaStreamNonBlocking);
        cudaEventCreateWithFlags(&evFork, cudaEventDisableTiming);
        cudaEventCreateWithFlags(&evJoin, cudaEventDisableTiming);
        cudaFuncSetAttribute(k_pairs, cudaFuncAttributeMaxDynamicSharedMemorySize, SMEM_K3);
    }

    cudaEventRecord(evFork, 0);
    cudaStreamWaitEvent(side, evFork, 0);
    k_m<<<DIM, DIM, 0, side>>>(W, b);
    cudaEventRecord(evJoin, side);

    k_mark<<<MARKBLOCKS, 256>>>(ui, ii);
    k_edge<<<(NUM_EDGES + 255) / 256, 256>>>(src, dst, uemb, iemb);

    cudaStreamWaitEvent(0, evJoin, 0);
    k_pairs<<<BATCH / BPB, 512, SMEM_K3>>>(ui, ii, out);
}